// round 6
// baseline (speedup 1.0000x reference)
#include <cuda_runtime.h>
#include <cuda_fp16.h>

// Problem constants (reference: B=2048, T=50, N=100, V=50000, D=512)
#define D_DIM 512
#define T_TGT 50
#define N_NOI 100
#define K_TOT 150
#define V_MAX 50000
#define MAX_B 4096
#define MAIN_GRID 592          // 148 SMs x 4 CTAs (persistent)

// Scratch (__device__ globals: allocation APIs are forbidden)
__device__ __half        g_Wh[(size_t)V_MAX * D_DIM];  // 51.2 MB fp16 copy of W
__device__ float         g_partials[MAX_B];
__device__ int           g_idx_stride;                 // 1 = int32 indices, 2 = int64 low word
__device__ unsigned int  g_count;                      // zero-init; reset by last CTA each call

__device__ __forceinline__ float log_sigmoid(float x) {
    return fminf(x, 0.0f) - __logf(1.0f + __expf(-fabsf(x)));
}

// Convert W (fp32) -> g_Wh (fp16). Streaming reads; fp16 table stays L2-resident.
// Also performs index-dtype detection.
__global__ void __launch_bounds__(256)
nsl_convert_kernel(const float* __restrict__ W, const int* __restrict__ t32, int nElem)
{
    if (blockIdx.x == 0 && threadIdx.x == 0) {
        int all_zero = 1;
        #pragma unroll
        for (int i = 0; i < 8; i++)
            if (t32[2 * i + 1] != 0) all_zero = 0;
        g_idx_stride = all_zero ? 2 : 1;   // int64 little-endian => odd words are 0
    }

    const float4* W4  = reinterpret_cast<const float4*>(W);
    uint4*        out = reinterpret_cast<uint4*>(g_Wh);
    const int n8     = nElem >> 3;            // one uint4 of halves per 8 floats
    const int stride = gridDim.x * blockDim.x;
    const int tid0   = blockIdx.x * blockDim.x + threadIdx.x;

    // 4 outputs per loop step: 8 independent streaming float4 loads in flight.
    for (int i = tid0; i < n8; i += 4 * stride) {
        int i1 = i + stride, i2 = i + 2 * stride, i3 = i + 3 * stride;

        float4 a0 = __ldcs(&W4[2 * i]);
        float4 a1 = __ldcs(&W4[2 * i + 1]);
        float4 b0, b1, c0, c1, d0, d1;
        if (i1 < n8) { b0 = __ldcs(&W4[2 * i1]); b1 = __ldcs(&W4[2 * i1 + 1]); }
        if (i2 < n8) { c0 = __ldcs(&W4[2 * i2]); c1 = __ldcs(&W4[2 * i2 + 1]); }
        if (i3 < n8) { d0 = __ldcs(&W4[2 * i3]); d1 = __ldcs(&W4[2 * i3 + 1]); }

        uint4 o; __half2 h;
        h = __floats2half2_rn(a0.x, a0.y); o.x = *reinterpret_cast<unsigned int*>(&h);
        h = __floats2half2_rn(a0.z, a0.w); o.y = *reinterpret_cast<unsigned int*>(&h);
        h = __floats2half2_rn(a1.x, a1.y); o.z = *reinterpret_cast<unsigned int*>(&h);
        h = __floats2half2_rn(a1.z, a1.w); o.w = *reinterpret_cast<unsigned int*>(&h);
        out[i] = o;
        if (i1 < n8) {
            h = __floats2half2_rn(b0.x, b0.y); o.x = *reinterpret_cast<unsigned int*>(&h);
            h = __floats2half2_rn(b0.z, b0.w); o.y = *reinterpret_cast<unsigned int*>(&h);
            h = __floats2half2_rn(b1.x, b1.y); o.z = *reinterpret_cast<unsigned int*>(&h);
            h = __floats2half2_rn(b1.z, b1.w); o.w = *reinterpret_cast<unsigned int*>(&h);
            out[i1] = o;
        }
        if (i2 < n8) {
            h = __floats2half2_rn(c0.x, c0.y); o.x = *reinterpret_cast<unsigned int*>(&h);
            h = __floats2half2_rn(c0.z, c0.w); o.y = *reinterpret_cast<unsigned int*>(&h);
            h = __floats2half2_rn(c1.x, c1.y); o.z = *reinterpret_cast<unsigned int*>(&h);
            h = __floats2half2_rn(c1.z, c1.w); o.w = *reinterpret_cast<unsigned int*>(&h);
            out[i2] = o;
        }
        if (i3 < n8) {
            h = __floats2half2_rn(d0.x, d0.y); o.x = *reinterpret_cast<unsigned int*>(&h);
            h = __floats2half2_rn(d0.z, d0.w); o.y = *reinterpret_cast<unsigned int*>(&h);
            h = __floats2half2_rn(d1.x, d1.y); o.z = *reinterpret_cast<unsigned int*>(&h);
            h = __floats2half2_rn(d1.z, d1.w); o.w = *reinterpret_cast<unsigned int*>(&h);
            out[i3] = o;
        }
    }
}

__device__ __forceinline__ __half2 u2h2(unsigned int u) {
    return *reinterpret_cast<__half2*>(&u);
}

__device__ __forceinline__ float dot_chunks(uint4 wa, uint4 wb, const __half2* fA, const __half2* fB) {
    __half2 acc = __float2half2_rn(0.0f);
    acc = __hfma2(u2h2(wa.x), fA[0], acc);
    acc = __hfma2(u2h2(wa.y), fA[1], acc);
    acc = __hfma2(u2h2(wa.z), fA[2], acc);
    acc = __hfma2(u2h2(wa.w), fA[3], acc);
    acc = __hfma2(u2h2(wb.x), fB[0], acc);
    acc = __hfma2(u2h2(wb.y), fB[1], acc);
    acc = __hfma2(u2h2(wb.z), fB[2], acc);
    acc = __hfma2(u2h2(wb.w), fB[3], acc);
    float2 af = __half22float2(acc);
    return af.x + af.y;
}

__global__ void __launch_bounds__(256)
nsl_main_kernel(const float* __restrict__ features,
                const int* __restrict__ targets,
                const int* __restrict__ noises,
                float* __restrict__ out, int B)
{
    const int tid  = threadIdx.x;
    const int warp = tid >> 5;
    const int lane = tid & 31;
    const int str  = g_idx_stride;

    __shared__ float wsum[32];
    __shared__ int   is_last;

    // Persistent loop over examples.
    for (int b = blockIdx.x; b < B; b += gridDim.x) {
        // Features for this lane's chunks as half2 registers.
        __half2 fA[4], fB[4];
        {
            const float4* f4 = reinterpret_cast<const float4*>(features + (size_t)b * D_DIM);
            float4 a0 = f4[2 * lane],      a1 = f4[2 * lane + 1];
            float4 b0 = f4[64 + 2 * lane], b1 = f4[65 + 2 * lane];
            fA[0] = __floats2half2_rn(a0.x, a0.y);
            fA[1] = __floats2half2_rn(a0.z, a0.w);
            fA[2] = __floats2half2_rn(a1.x, a1.y);
            fA[3] = __floats2half2_rn(a1.z, a1.w);
            fB[0] = __floats2half2_rn(b0.x, b0.y);
            fB[1] = __floats2half2_rn(b0.z, b0.w);
            fB[2] = __floats2half2_rn(b1.x, b1.y);
            fB[3] = __floats2half2_rn(b1.z, b1.w);
        }

        const int* tg = targets + (size_t)b * T_TGT * str;
        const int* ns = noises  + (size_t)b * N_NOI * str;

        // Lane r preloads the index for row k = warp + 8*r.
        const int count = (K_TOT - warp + 7) >> 3;   // 19 (warps 0-5) or 18 (warps 6-7)
        int myidx = 0;
        {
            int k = warp + lane * 8;
            if (k < K_TOT)
                myidx = (k < T_TGT) ? tg[k * str] : ns[(k - T_TGT) * str];
        }

        float local = 0.0f;   // meaningful on lanes 0, 8, 16, 24

        const int ngroups = count >> 2;
        for (int p = 0; p < ngroups; p++) {
            int r = 4 * p;
            int i0 = __shfl_sync(0xFFFFFFFFu, myidx, r);
            int i1 = __shfl_sync(0xFFFFFFFFu, myidx, r + 1);
            int i2 = __shfl_sync(0xFFFFFFFFu, myidx, r + 2);
            int i3 = __shfl_sync(0xFFFFFFFFu, myidx, r + 3);

            const uint4* w0 = reinterpret_cast<const uint4*>(g_Wh + (size_t)i0 * D_DIM);
            const uint4* w1 = reinterpret_cast<const uint4*>(g_Wh + (size_t)i1 * D_DIM);
            const uint4* w2 = reinterpret_cast<const uint4*>(g_Wh + (size_t)i2 * D_DIM);
            const uint4* w3 = reinterpret_cast<const uint4*>(g_Wh + (size_t)i3 * D_DIM);

            uint4 a0 = __ldcg(&w0[lane]), b0c = __ldcg(&w0[32 + lane]);
            uint4 a1 = __ldcg(&w1[lane]), b1c = __ldcg(&w1[32 + lane]);
            uint4 a2 = __ldcg(&w2[lane]), b2c = __ldcg(&w2[32 + lane]);
            uint4 a3 = __ldcg(&w3[lane]), b3c = __ldcg(&w3[32 + lane]);

            float s0 = dot_chunks(a0, b0c, fA, fB);
            float s1 = dot_chunks(a1, b1c, fA, fB);
            float s2 = dot_chunks(a2, b2c, fA, fB);
            float s3 = dot_chunks(a3, b3c, fA, fB);

            // 4-way merged butterfly: 9 shuffles total.
            s0 += __shfl_xor_sync(0xFFFFFFFFu, s0, 16);
            s1 += __shfl_xor_sync(0xFFFFFFFFu, s1, 16);
            s2 += __shfl_xor_sync(0xFFFFFFFFu, s2, 16);
            s3 += __shfl_xor_sync(0xFFFFFFFFu, s3, 16);
            float m01 = (lane < 16) ? s0 : s1;
            float m23 = (lane < 16) ? s2 : s3;
            m01 += __shfl_xor_sync(0xFFFFFFFFu, m01, 8);
            m23 += __shfl_xor_sync(0xFFFFFFFFu, m23, 8);
            float m = (lane & 8) ? m23 : m01;
            m += __shfl_xor_sync(0xFFFFFFFFu, m, 4);
            m += __shfl_xor_sync(0xFFFFFFFFu, m, 2);
            m += __shfl_xor_sync(0xFFFFFFFFu, m, 1);

            // lanes 0,8,16,24 hold rows r0, r2, r1, r3 respectively.
            if ((lane & 7) == 0) {
                int sel = lane >> 3;
                int roff = (sel == 1) ? 16 : (sel == 2) ? 8 : (sel == 3) ? 24 : 0;
                int k = warp + 32 * p + roff;
                float sgn = (k < T_TGT) ? 1.0f : -1.0f;
                local += log_sigmoid(sgn * m);
            }
        }

        int r = ngroups * 4;
        if (r + 1 < count) {   // pair
            int i0 = __shfl_sync(0xFFFFFFFFu, myidx, r);
            int i1 = __shfl_sync(0xFFFFFFFFu, myidx, r + 1);
            const uint4* w0 = reinterpret_cast<const uint4*>(g_Wh + (size_t)i0 * D_DIM);
            const uint4* w1 = reinterpret_cast<const uint4*>(g_Wh + (size_t)i1 * D_DIM);
            uint4 a0 = __ldcg(&w0[lane]), b0c = __ldcg(&w0[32 + lane]);
            uint4 a1 = __ldcg(&w1[lane]), b1c = __ldcg(&w1[32 + lane]);
            float s0 = dot_chunks(a0, b0c, fA, fB);
            float s1 = dot_chunks(a1, b1c, fA, fB);
            s0 += __shfl_xor_sync(0xFFFFFFFFu, s0, 16);
            s1 += __shfl_xor_sync(0xFFFFFFFFu, s1, 16);
            float m = (lane < 16) ? s0 : s1;
            #pragma unroll
            for (int o = 8; o > 0; o >>= 1)
                m += __shfl_xor_sync(0xFFFFFFFFu, m, o);
            if ((lane & 15) == 0) {
                int k = warp + ((lane == 0) ? r : (r + 1)) * 8;
                float sgn = (k < T_TGT) ? 1.0f : -1.0f;
                local += log_sigmoid(sgn * m);
            }
            r += 2;
        }
        if (r < count) {       // single
            int i0 = __shfl_sync(0xFFFFFFFFu, myidx, r);
            const uint4* w0 = reinterpret_cast<const uint4*>(g_Wh + (size_t)i0 * D_DIM);
            uint4 a0 = __ldcg(&w0[lane]), b0c = __ldcg(&w0[32 + lane]);
            float s0 = dot_chunks(a0, b0c, fA, fB);
            #pragma unroll
            for (int o = 16; o > 0; o >>= 1)
                s0 += __shfl_xor_sync(0xFFFFFFFFu, s0, o);
            if (lane == 0) {
                int k = warp + r * 8;
                float sgn = (k < T_TGT) ? 1.0f : -1.0f;
                local += log_sigmoid(sgn * s0);
            }
        }

        if ((lane & 7) == 0)
            wsum[4 * warp + (lane >> 3)] = local;
        __syncthreads();

        if (tid == 0) {
            float s = 0.0f;
            #pragma unroll
            for (int w = 0; w < 32; w++) s += wsum[w];
            g_partials[b] = s;
        }
        __syncthreads();   // wsum reusable next iteration
    }

    // CTA-completion accounting; last CTA does the deterministic final reduce.
    if (tid == 0) {
        __threadfence();
        unsigned v = atomicAdd(&g_count, 1u);
        is_last = (v == (unsigned)(gridDim.x - 1)) ? 1 : 0;
    }
    __syncthreads();

    if (is_last) {
        __shared__ float red[256];
        __threadfence();
        float s = 0.0f;
        for (int i = tid; i < B; i += 256)
            s += g_partials[i];
        red[tid] = s;
        __syncthreads();
        #pragma unroll
        for (int stride = 128; stride > 0; stride >>= 1) {
            if (tid < stride) red[tid] += red[tid + stride];
            __syncthreads();
        }
        if (tid == 0) {
            out[0] = -red[0] / (float)K_TOT;
            g_count = 0;   // reset for next graph replay
        }
    }
}

extern "C" void kernel_launch(void* const* d_in, const int* in_sizes, int n_in,
                              void* d_out, int out_size)
{
    const float* features = (const float*)d_in[0];
    const int*   targets  = (const int*)d_in[1];
    const int*   noises   = (const int*)d_in[2];
    const float* W        = (const float*)d_in[3];

    const int B      = in_sizes[0] / D_DIM;       // 2048
    const int nElemW = in_sizes[3];               // 50000*512

    nsl_convert_kernel<<<2368, 256>>>(W, targets, nElemW);
    nsl_main_kernel<<<MAIN_GRID, 256>>>(features, targets, noises, (float*)d_out, B);
}

// round 7
// speedup vs baseline: 1.1379x; 1.1379x over previous
#include <cuda_runtime.h>
#include <cuda_fp16.h>

// Problem constants (reference: B=2048, T=50, N=100, V=50000, D=512)
#define D_DIM 512
#define T_TGT 50
#define N_NOI 100
#define K_TOT 150
#define V_MAX 50000
#define MAX_B 4096

// Scratch (__device__ globals: allocation APIs are forbidden)
__device__ signed char   g_Wq[(size_t)V_MAX * D_DIM];  // 25.6 MB int8 copy of W
__device__ float         g_Wscale[V_MAX];              // per-row scale
__device__ float         g_partials[MAX_B];
__device__ int           g_idx_stride;                 // 1 = int32 indices, 2 = int64 low word
__device__ unsigned int  g_count;                      // zero-init; reset by last block each call

__device__ __forceinline__ float log_sigmoid(float x) {
    return fminf(x, 0.0f) - __logf(1.0f + __expf(-fabsf(x)));
}

__device__ __forceinline__ unsigned pack4(float x, float y, float z, float w, float inv) {
    int b0 = __float2int_rn(x * inv);
    int b1 = __float2int_rn(y * inv);
    int b2 = __float2int_rn(z * inv);
    int b3 = __float2int_rn(w * inv);
    return (unsigned)(b0 & 0xFF) | ((unsigned)(b1 & 0xFF) << 8) |
           ((unsigned)(b2 & 0xFF) << 16) | ((unsigned)b3 << 24);
}

// Quantize W (fp32) -> g_Wq (int8, per-row scale) + g_Wscale.
// One warp per row: coalesced float4 reads, max-reduce, coalesced int32 writes.
// Also performs index-dtype detection.
__global__ void __launch_bounds__(256)
nsl_convert_kernel(const float* __restrict__ W, const int* __restrict__ t32, int nRows)
{
    if (blockIdx.x == 0 && threadIdx.x == 0) {
        int all_zero = 1;
        #pragma unroll
        for (int i = 0; i < 8; i++)
            if (t32[2 * i + 1] != 0) all_zero = 0;
        g_idx_stride = all_zero ? 2 : 1;   // int64 little-endian => odd words are 0
    }

    const int warp = threadIdx.x >> 5;
    const int lane = threadIdx.x & 31;
    const int row  = blockIdx.x * 8 + warp;
    if (row >= nRows) return;

    const float4* src = reinterpret_cast<const float4*>(W + (size_t)row * D_DIM);
    float4 v[4];
    #pragma unroll
    for (int j = 0; j < 4; j++)
        v[j] = __ldcs(&src[j * 32 + lane]);    // elements 4*(j*32+lane) .. +3

    float m = 0.0f;
    #pragma unroll
    for (int j = 0; j < 4; j++) {
        m = fmaxf(m, fabsf(v[j].x)); m = fmaxf(m, fabsf(v[j].y));
        m = fmaxf(m, fabsf(v[j].z)); m = fmaxf(m, fabsf(v[j].w));
    }
    #pragma unroll
    for (int o = 16; o > 0; o >>= 1)
        m = fmaxf(m, __shfl_xor_sync(0xFFFFFFFFu, m, o));

    const float inv = (m > 0.0f) ? 127.0f / m : 0.0f;

    int* dst = reinterpret_cast<int*>(g_Wq + (size_t)row * D_DIM);
    #pragma unroll
    for (int j = 0; j < 4; j++)
        dst[j * 32 + lane] = (int)pack4(v[j].x, v[j].y, v[j].z, v[j].w, inv);

    if (lane == 0)
        g_Wscale[row] = m * (1.0f / 127.0f);
}

// 16 int8 x 16 int8 exact dot via 4 dp4a.
__device__ __forceinline__ int dot16(uint4 w, const int* fq) {
    int acc = 0;
    acc = __dp4a((int)w.x, fq[0], acc);
    acc = __dp4a((int)w.y, fq[1], acc);
    acc = __dp4a((int)w.z, fq[2], acc);
    acc = __dp4a((int)w.w, fq[3], acc);
    return acc;
}

__global__ void __launch_bounds__(256)
nsl_main_kernel(const float* __restrict__ features,
                const int* __restrict__ targets,
                const int* __restrict__ noises,
                float* __restrict__ out, int B)
{
    const int b    = blockIdx.x;
    const int tid  = threadIdx.x;
    const int warp = tid >> 5;
    const int lane = tid & 31;
    const int str  = g_idx_stride;

    __shared__ float wsum[32];
    __shared__ int   is_last;

    // ---- Per-example feature quantization (each warp redundantly, registers only).
    // Lane owns feature elements [16*lane, 16*lane+16) to match W's 16B/lane layout.
    float sf;
    int fq[4];
    {
        const float4* f4 = reinterpret_cast<const float4*>(features + (size_t)b * D_DIM);
        float4 fv[4];
        #pragma unroll
        for (int j = 0; j < 4; j++)
            fv[j] = f4[4 * lane + j];          // elements 16*lane + 4j .. +3

        float mf = 0.0f;
        #pragma unroll
        for (int j = 0; j < 4; j++) {
            mf = fmaxf(mf, fabsf(fv[j].x)); mf = fmaxf(mf, fabsf(fv[j].y));
            mf = fmaxf(mf, fabsf(fv[j].z)); mf = fmaxf(mf, fabsf(fv[j].w));
        }
        #pragma unroll
        for (int o = 16; o > 0; o >>= 1)
            mf = fmaxf(mf, __shfl_xor_sync(0xFFFFFFFFu, mf, o));

        const float invf = (mf > 0.0f) ? 127.0f / mf : 0.0f;
        sf = mf * (1.0f / 127.0f);
        #pragma unroll
        for (int j = 0; j < 4; j++)
            fq[j] = (int)pack4(fv[j].x, fv[j].y, fv[j].z, fv[j].w, invf);
    }

    const int* tg = targets + (size_t)b * T_TGT * str;
    const int* ns = noises  + (size_t)b * N_NOI * str;

    // Lane r preloads the index for row k = warp + 8*r.
    const int count = (K_TOT - warp + 7) >> 3;   // 19 (warps 0-5) or 18 (warps 6-7)
    int myidx = 0;
    {
        int k = warp + lane * 8;
        if (k < K_TOT)
            myidx = (k < T_TGT) ? tg[k * str] : ns[(k - T_TGT) * str];
    }

    float local = 0.0f;   // meaningful on lanes 0, 8, 16, 24

    // ---- Groups of 4 rows: 4 independent LDG.128 in flight, exact int math ----
    const int ngroups = count >> 2;
    for (int p = 0; p < ngroups; p++) {
        int r = 4 * p;
        int i0 = __shfl_sync(0xFFFFFFFFu, myidx, r);
        int i1 = __shfl_sync(0xFFFFFFFFu, myidx, r + 1);
        int i2 = __shfl_sync(0xFFFFFFFFu, myidx, r + 2);
        int i3 = __shfl_sync(0xFFFFFFFFu, myidx, r + 3);

        uint4 a0 = __ldcg(&reinterpret_cast<const uint4*>(g_Wq + (size_t)i0 * D_DIM)[lane]);
        uint4 a1 = __ldcg(&reinterpret_cast<const uint4*>(g_Wq + (size_t)i1 * D_DIM)[lane]);
        uint4 a2 = __ldcg(&reinterpret_cast<const uint4*>(g_Wq + (size_t)i2 * D_DIM)[lane]);
        uint4 a3 = __ldcg(&reinterpret_cast<const uint4*>(g_Wq + (size_t)i3 * D_DIM)[lane]);

        int s0 = dot16(a0, fq);
        int s1 = dot16(a1, fq);
        int s2 = dot16(a2, fq);
        int s3 = dot16(a3, fq);

        // 4-way merged integer butterfly: 9 shuffles total (exact).
        s0 += __shfl_xor_sync(0xFFFFFFFFu, s0, 16);
        s1 += __shfl_xor_sync(0xFFFFFFFFu, s1, 16);
        s2 += __shfl_xor_sync(0xFFFFFFFFu, s2, 16);
        s3 += __shfl_xor_sync(0xFFFFFFFFu, s3, 16);
        int m01 = (lane < 16) ? s0 : s1;
        int m23 = (lane < 16) ? s2 : s3;
        m01 += __shfl_xor_sync(0xFFFFFFFFu, m01, 8);
        m23 += __shfl_xor_sync(0xFFFFFFFFu, m23, 8);
        int m = (lane & 8) ? m23 : m01;
        m += __shfl_xor_sync(0xFFFFFFFFu, m, 4);
        m += __shfl_xor_sync(0xFFFFFFFFu, m, 2);
        m += __shfl_xor_sync(0xFFFFFFFFu, m, 1);

        // lanes 0,8,16,24 hold rows r+0, r+2, r+1, r+3 respectively.
        int sel = lane >> 3;
        int rowsel = (sel == 1) ? 2 : (sel == 2) ? 1 : (sel == 3) ? 3 : 0;
        int idxr = __shfl_sync(0xFFFFFFFFu, myidx, r + rowsel);
        if ((lane & 7) == 0) {
            float sw = g_Wscale[idxr];
            int k = warp + 8 * (r + rowsel);
            float sgn = (k < T_TGT) ? 1.0f : -1.0f;
            local += log_sigmoid(sgn * (float)m * (sw * sf));
        }
    }

    // ---- Remainder rows (2 or 3) ----
    int r = ngroups * 4;
    if (r + 1 < count) {   // pair
        int i0 = __shfl_sync(0xFFFFFFFFu, myidx, r);
        int i1 = __shfl_sync(0xFFFFFFFFu, myidx, r + 1);
        uint4 a0 = __ldcg(&reinterpret_cast<const uint4*>(g_Wq + (size_t)i0 * D_DIM)[lane]);
        uint4 a1 = __ldcg(&reinterpret_cast<const uint4*>(g_Wq + (size_t)i1 * D_DIM)[lane]);
        int s0 = dot16(a0, fq);
        int s1 = dot16(a1, fq);
        s0 += __shfl_xor_sync(0xFFFFFFFFu, s0, 16);
        s1 += __shfl_xor_sync(0xFFFFFFFFu, s1, 16);
        int m = (lane < 16) ? s0 : s1;
        #pragma unroll
        for (int o = 8; o > 0; o >>= 1)
            m += __shfl_xor_sync(0xFFFFFFFFu, m, o);
        int rowsel = (lane >= 16) ? 1 : 0;
        int idxr = __shfl_sync(0xFFFFFFFFu, myidx, r + rowsel);
        if ((lane & 15) == 0) {
            float sw = g_Wscale[idxr];
            int k = warp + 8 * (r + rowsel);
            float sgn = (k < T_TGT) ? 1.0f : -1.0f;
            local += log_sigmoid(sgn * (float)m * (sw * sf));
        }
        r += 2;
    }
    if (r < count) {       // single
        int i0 = __shfl_sync(0xFFFFFFFFu, myidx, r);
        uint4 a0 = __ldcg(&reinterpret_cast<const uint4*>(g_Wq + (size_t)i0 * D_DIM)[lane]);
        int s0 = dot16(a0, fq);
        #pragma unroll
        for (int o = 16; o > 0; o >>= 1)
            s0 += __shfl_xor_sync(0xFFFFFFFFu, s0, o);
        if (lane == 0) {
            float sw = g_Wscale[i0];
            int k = warp + r * 8;
            float sgn = (k < T_TGT) ? 1.0f : -1.0f;
            local += log_sigmoid(sgn * (float)s0 * (sw * sf));
        }
    }

    if ((lane & 7) == 0)
        wsum[4 * warp + (lane >> 3)] = local;
    __syncthreads();

    if (tid == 0) {
        float s = 0.0f;
        #pragma unroll
        for (int w = 0; w < 32; w++) s += wsum[w];
        g_partials[b] = s;
        __threadfence();
        unsigned v = atomicAdd(&g_count, 1u);
        is_last = (v == (unsigned)(gridDim.x - 1)) ? 1 : 0;
    }
    __syncthreads();

    // Last finished block performs the deterministic final reduction.
    if (is_last) {
        __shared__ float red[256];
        __threadfence();
        float s = 0.0f;
        for (int i = tid; i < B; i += 256)
            s += g_partials[i];
        red[tid] = s;
        __syncthreads();
        #pragma unroll
        for (int stride = 128; stride > 0; stride >>= 1) {
            if (tid < stride) red[tid] += red[tid + stride];
            __syncthreads();
        }
        if (tid == 0) {
            out[0] = -red[0] / (float)K_TOT;
            g_count = 0;   // reset for next graph replay
        }
    }
}

extern "C" void kernel_launch(void* const* d_in, const int* in_sizes, int n_in,
                              void* d_out, int out_size)
{
    const float* features = (const float*)d_in[0];
    const int*   targets  = (const int*)d_in[1];
    const int*   noises   = (const int*)d_in[2];
    const float* W        = (const float*)d_in[3];

    const int B     = in_sizes[0] / D_DIM;        // 2048
    const int nRows = in_sizes[3] / D_DIM;        // 50000

    nsl_convert_kernel<<<(nRows + 7) / 8, 256>>>(W, targets, nRows);
    nsl_main_kernel<<<B, 256>>>(features, targets, noises, (float*)d_out, B);
}

// round 9
// speedup vs baseline: 1.1601x; 1.0194x over previous
#include <cuda_runtime.h>
#include <cuda_fp16.h>

// Problem constants (reference: B=2048, T=50, N=100, V=50000, D=512)
#define D_DIM 512
#define T_TGT 50
#define N_NOI 100
#define K_TOT 150
#define V_MAX 50000
#define MAX_B 4096

// Scratch (__device__ globals: allocation APIs are forbidden)
__device__ signed char   g_Wq[(size_t)V_MAX * D_DIM];  // 25.6 MB int8 copy of W
__device__ float         g_Wscale[V_MAX];              // per-row scale
__device__ float         g_partials[MAX_B];
__device__ int           g_idx_stride;                 // 1 = int32 indices, 2 = int64 low word
__device__ unsigned int  g_count;                      // zero-init; reset by last block each call

__device__ __forceinline__ float log_sigmoid(float x) {
    return fminf(x, 0.0f) - __logf(1.0f + __expf(-fabsf(x)));
}

__device__ __forceinline__ unsigned pack4(float x, float y, float z, float w, float inv) {
    int b0 = __float2int_rn(x * inv);
    int b1 = __float2int_rn(y * inv);
    int b2 = __float2int_rn(z * inv);
    int b3 = __float2int_rn(w * inv);
    return (unsigned)(b0 & 0xFF) | ((unsigned)(b1 & 0xFF) << 8) |
           ((unsigned)(b2 & 0xFF) << 16) | ((unsigned)b3 << 24);
}

// Quantize W (fp32) -> g_Wq (int8, per-row scale) + g_Wscale.
// One warp per row. Also performs index-dtype detection.
__global__ void __launch_bounds__(256)
nsl_convert_kernel(const float* __restrict__ W, const int* __restrict__ t32, int nRows)
{
    if (blockIdx.x == 0 && threadIdx.x == 0) {
        int all_zero = 1;
        #pragma unroll
        for (int i = 0; i < 8; i++)
            if (t32[2 * i + 1] != 0) all_zero = 0;
        g_idx_stride = all_zero ? 2 : 1;   // int64 little-endian => odd words are 0
    }

    const int warp = threadIdx.x >> 5;
    const int lane = threadIdx.x & 31;
    const int row  = blockIdx.x * 8 + warp;
    if (row >= nRows) return;

    const float4* src = reinterpret_cast<const float4*>(W + (size_t)row * D_DIM);
    float4 v[4];
    #pragma unroll
    for (int j = 0; j < 4; j++)
        v[j] = __ldcs(&src[j * 32 + lane]);

    float m = 0.0f;
    #pragma unroll
    for (int j = 0; j < 4; j++) {
        m = fmaxf(m, fabsf(v[j].x)); m = fmaxf(m, fabsf(v[j].y));
        m = fmaxf(m, fabsf(v[j].z)); m = fmaxf(m, fabsf(v[j].w));
    }
    #pragma unroll
    for (int o = 16; o > 0; o >>= 1)
        m = fmaxf(m, __shfl_xor_sync(0xFFFFFFFFu, m, o));

    const float inv = (m > 0.0f) ? 127.0f / m : 0.0f;

    int* dst = reinterpret_cast<int*>(g_Wq + (size_t)row * D_DIM);
    #pragma unroll
    for (int j = 0; j < 4; j++)
        dst[j * 32 + lane] = (int)pack4(v[j].x, v[j].y, v[j].z, v[j].w, inv);

    if (lane == 0)
        g_Wscale[row] = m * (1.0f / 127.0f);
}

// 16 int8 x 16 int8 exact dot via 4 dp4a.
__device__ __forceinline__ int dot16(uint4 w, const int* fq) {
    int acc = 0;
    acc = __dp4a((int)w.x, fq[0], acc);
    acc = __dp4a((int)w.y, fq[1], acc);
    acc = __dp4a((int)w.z, fq[2], acc);
    acc = __dp4a((int)w.w, fq[3], acc);
    return acc;
}

__global__ void __launch_bounds__(256)
nsl_main_kernel(const float* __restrict__ features,
                const int* __restrict__ targets,
                const int* __restrict__ noises,
                float* __restrict__ out, int B)
{
    const int b    = blockIdx.x;
    const int tid  = threadIdx.x;
    const int warp = tid >> 5;
    const int lane = tid & 31;
    const int str  = g_idx_stride;

    __shared__ float wsum[64];
    __shared__ int   is_last;

    // ---- Per-example feature quantization (registers only).
    // Lane owns feature elements [16*lane, 16*lane+16).
    float sf;
    int fq[4];
    {
        const float4* f4 = reinterpret_cast<const float4*>(features + (size_t)b * D_DIM);
        float4 fv[4];
        #pragma unroll
        for (int j = 0; j < 4; j++)
            fv[j] = f4[4 * lane + j];

        float mf = 0.0f;
        #pragma unroll
        for (int j = 0; j < 4; j++) {
            mf = fmaxf(mf, fabsf(fv[j].x)); mf = fmaxf(mf, fabsf(fv[j].y));
            mf = fmaxf(mf, fabsf(fv[j].z)); mf = fmaxf(mf, fabsf(fv[j].w));
        }
        #pragma unroll
        for (int o = 16; o > 0; o >>= 1)
            mf = fmaxf(mf, __shfl_xor_sync(0xFFFFFFFFu, mf, o));

        const float invf = (mf > 0.0f) ? 127.0f / mf : 0.0f;
        sf = mf * (1.0f / 127.0f);
        #pragma unroll
        for (int j = 0; j < 4; j++)
            fq[j] = (int)pack4(fv[j].x, fv[j].y, fv[j].z, fv[j].w, invf);
    }

    const int* tg = targets + (size_t)b * T_TGT * str;
    const int* ns = noises  + (size_t)b * N_NOI * str;

    // Lane r preloads the index for row k = warp + 8*r.
    const int count = (K_TOT - warp + 7) >> 3;   // 19 (warps 0-5) or 18 (warps 6-7)
    int myidx = 0;
    {
        int k = warp + lane * 8;
        if (k < K_TOT)
            myidx = (k < T_TGT) ? tg[k * str] : ns[(k - T_TGT) * str];
    }

    float local = 0.0f;

    // ---- Groups of 8 rows: 8 independent LDG.128 in flight ----
    const int ngroups = count >> 3;              // 2
    for (int p = 0; p < ngroups; p++) {
        const int r = 8 * p;
        int s[8];
        #pragma unroll
        for (int q = 0; q < 8; q++) {
            int idx = __shfl_sync(0xFFFFFFFFu, myidx, r + q);
            uint4 a = __ldcg(&reinterpret_cast<const uint4*>(g_Wq + (size_t)idx * D_DIM)[lane]);
            s[q] = dot16(a, fq);
        }

        // 8-way merged integer butterfly: 16 shuffles.
        #pragma unroll
        for (int q = 0; q < 8; q++)
            s[q] += __shfl_xor_sync(0xFFFFFFFFu, s[q], 16);
        int m0 = (lane & 16) ? s[1] : s[0];
        int m1 = (lane & 16) ? s[3] : s[2];
        int m2 = (lane & 16) ? s[5] : s[4];
        int m3 = (lane & 16) ? s[7] : s[6];
        m0 += __shfl_xor_sync(0xFFFFFFFFu, m0, 8);
        m1 += __shfl_xor_sync(0xFFFFFFFFu, m1, 8);
        m2 += __shfl_xor_sync(0xFFFFFFFFu, m2, 8);
        m3 += __shfl_xor_sync(0xFFFFFFFFu, m3, 8);
        int n0 = (lane & 8) ? m1 : m0;
        int n1 = (lane & 8) ? m3 : m2;
        n0 += __shfl_xor_sync(0xFFFFFFFFu, n0, 4);
        n1 += __shfl_xor_sync(0xFFFFFFFFu, n1, 4);
        int v = (lane & 4) ? n1 : n0;
        v += __shfl_xor_sync(0xFFFFFFFFu, v, 2);
        v += __shfl_xor_sync(0xFFFFFFFFu, v, 1);

        // Lane 4a (a=0..7) holds row rsel = 4*bit2 + 2*bit3 + bit4 of lane.
        // Full-mask shuffle, executed by ALL lanes (fix for R8's partial-mask UB).
        int rsel = ((lane >> 2) & 1) * 4 + ((lane >> 3) & 1) * 2 + ((lane >> 4) & 1);
        int idxr = __shfl_sync(0xFFFFFFFFu, myidx, r + rsel);
        if ((lane & 3) == 0) {
            float sw = g_Wscale[idxr];
            int k = warp + 8 * (r + rsel);
            float sgn = (k < T_TGT) ? 1.0f : -1.0f;
            local += log_sigmoid(sgn * (float)v * (sw * sf));
        }
    }

    // ---- Remainder rows (2 or 3) ----
    int r = ngroups * 8;
    if (r + 1 < count) {   // pair
        int i0 = __shfl_sync(0xFFFFFFFFu, myidx, r);
        int i1 = __shfl_sync(0xFFFFFFFFu, myidx, r + 1);
        uint4 a0 = __ldcg(&reinterpret_cast<const uint4*>(g_Wq + (size_t)i0 * D_DIM)[lane]);
        uint4 a1 = __ldcg(&reinterpret_cast<const uint4*>(g_Wq + (size_t)i1 * D_DIM)[lane]);
        int s0 = dot16(a0, fq);
        int s1 = dot16(a1, fq);
        s0 += __shfl_xor_sync(0xFFFFFFFFu, s0, 16);
        s1 += __shfl_xor_sync(0xFFFFFFFFu, s1, 16);
        int m = (lane < 16) ? s0 : s1;
        #pragma unroll
        for (int o = 8; o > 0; o >>= 1)
            m += __shfl_xor_sync(0xFFFFFFFFu, m, o);
        int rowsel = (lane >= 16) ? 1 : 0;
        int idxr = __shfl_sync(0xFFFFFFFFu, myidx, r + rowsel);
        if ((lane & 15) == 0) {
            float sw = g_Wscale[idxr];
            int k = warp + 8 * (r + rowsel);
            float sgn = (k < T_TGT) ? 1.0f : -1.0f;
            local += log_sigmoid(sgn * (float)m * (sw * sf));
        }
        r += 2;
    }
    if (r < count) {       // single
        int i0 = __shfl_sync(0xFFFFFFFFu, myidx, r);
        uint4 a0 = __ldcg(&reinterpret_cast<const uint4*>(g_Wq + (size_t)i0 * D_DIM)[lane]);
        int s0 = dot16(a0, fq);
        #pragma unroll
        for (int o = 16; o > 0; o >>= 1)
            s0 += __shfl_xor_sync(0xFFFFFFFFu, s0, o);
        if (lane == 0) {
            float sw = g_Wscale[i0];
            int k = warp + r * 8;
            float sgn = (k < T_TGT) ? 1.0f : -1.0f;
            local += log_sigmoid(sgn * (float)s0 * (sw * sf));
        }
    }

    if ((lane & 3) == 0)
        wsum[8 * warp + (lane >> 2)] = local;
    __syncthreads();

    if (tid == 0) {
        float s = 0.0f;
        #pragma unroll
        for (int w = 0; w < 64; w++) s += wsum[w];
        g_partials[b] = s;
        __threadfence();
        unsigned v = atomicAdd(&g_count, 1u);
        is_last = (v == (unsigned)(gridDim.x - 1)) ? 1 : 0;
    }
    __syncthreads();

    // Last finished block performs the deterministic final reduction.
    if (is_last) {
        __shared__ float red[256];
        __threadfence();
        float s = 0.0f;
        for (int i = tid; i < B; i += 256)
            s += g_partials[i];
        red[tid] = s;
        __syncthreads();
        #pragma unroll
        for (int stride = 128; stride > 0; stride >>= 1) {
            if (tid < stride) red[tid] += red[tid + stride];
            __syncthreads();
        }
        if (tid == 0) {
            out[0] = -red[0] / (float)K_TOT;
            g_count = 0;   // reset for next graph replay
        }
    }
}

extern "C" void kernel_launch(void* const* d_in, const int* in_sizes, int n_in,
                              void* d_out, int out_size)
{
    const float* features = (const float*)d_in[0];
    const int*   targets  = (const int*)d_in[1];
    const int*   noises   = (const int*)d_in[2];
    const float* W        = (const float*)d_in[3];

    const int B     = in_sizes[0] / D_DIM;        // 2048
    const int nRows = in_sizes[3] / D_DIM;        // 50000

    nsl_convert_kernel<<<(nRows + 7) / 8, 256>>>(W, targets, nRows);
    nsl_main_kernel<<<B, 256>>>(features, targets, noises, (float*)d_out, B);
}

// round 10
// speedup vs baseline: 1.1894x; 1.0253x over previous
#include <cuda_runtime.h>
#include <cuda_fp16.h>

// Problem constants (reference: B=2048, T=50, N=100, V=50000, D=512)
#define D_DIM 512
#define T_TGT 50
#define N_NOI 100
#define K_TOT 150
#define V_MAX 50000
#define MAX_B 4096

// Scratch (__device__ globals: allocation APIs are forbidden)
__device__ signed char   g_Wq[(size_t)V_MAX * D_DIM];  // 25.6 MB int8 copy of W
__device__ float         g_Wscale[V_MAX];              // per-row W scale
__device__ signed char   g_fq[(size_t)MAX_B * D_DIM];  // int8 quantized features
__device__ float         g_fscale[MAX_B];              // per-example feature scale
__device__ float         g_partials[MAX_B];
__device__ int           g_idx_stride;                 // 1 = int32 indices, 2 = int64 low word
__device__ unsigned int  g_count;                      // zero-init; reset by last block each call

__device__ __forceinline__ float log_sigmoid(float x) {
    return fminf(x, 0.0f) - __logf(1.0f + __expf(-fabsf(x)));
}

__device__ __forceinline__ unsigned pack4(float x, float y, float z, float w, float inv) {
    int b0 = __float2int_rn(x * inv);
    int b1 = __float2int_rn(y * inv);
    int b2 = __float2int_rn(z * inv);
    int b3 = __float2int_rn(w * inv);
    return (unsigned)(b0 & 0xFF) | ((unsigned)(b1 & 0xFF) << 8) |
           ((unsigned)(b2 & 0xFF) << 16) | ((unsigned)b3 << 24);
}

// One warp quantizes one length-512 fp32 vector to int8 with a single scale.
// Lane owns elements [16*lane, 16*lane+16). Layout matches the main kernel's
// uint4-per-lane access pattern exactly.
__device__ __forceinline__ void quant_row_warp(const float* __restrict__ src,
                                               signed char* __restrict__ dst,
                                               float* __restrict__ scale_out,
                                               int lane, bool streaming)
{
    const float4* s4 = reinterpret_cast<const float4*>(src);
    float4 v[4];
    #pragma unroll
    for (int j = 0; j < 4; j++)
        v[j] = streaming ? __ldcs(&s4[4 * lane + j]) : s4[4 * lane + j];

    float m = 0.0f;
    #pragma unroll
    for (int j = 0; j < 4; j++) {
        m = fmaxf(m, fabsf(v[j].x)); m = fmaxf(m, fabsf(v[j].y));
        m = fmaxf(m, fabsf(v[j].z)); m = fmaxf(m, fabsf(v[j].w));
    }
    #pragma unroll
    for (int o = 16; o > 0; o >>= 1)
        m = fmaxf(m, __shfl_xor_sync(0xFFFFFFFFu, m, o));

    const float inv = (m > 0.0f) ? 127.0f / m : 0.0f;

    uint4 o4;
    o4.x = pack4(v[0].x, v[0].y, v[0].z, v[0].w, inv);
    o4.y = pack4(v[1].x, v[1].y, v[1].z, v[1].w, inv);
    o4.z = pack4(v[2].x, v[2].y, v[2].z, v[2].w, inv);
    o4.w = pack4(v[3].x, v[3].y, v[3].z, v[3].w, inv);
    reinterpret_cast<uint4*>(dst)[lane] = o4;

    if (lane == 0)
        *scale_out = m * (1.0f / 127.0f);
}

// Blocks [0, nRowBlocks): quantize W rows. Blocks [nRowBlocks, ...): quantize features.
// Block 0 thread 0 additionally detects index dtype.
__global__ void __launch_bounds__(256)
nsl_convert_kernel(const float* __restrict__ W, const float* __restrict__ features,
                   const int* __restrict__ t32, int nRows, int nRowBlocks, int B)
{
    if (blockIdx.x == 0 && threadIdx.x == 0) {
        int all_zero = 1;
        #pragma unroll
        for (int i = 0; i < 8; i++)
            if (t32[2 * i + 1] != 0) all_zero = 0;
        g_idx_stride = all_zero ? 2 : 1;   // int64 little-endian => odd words are 0
    }

    const int warp = threadIdx.x >> 5;
    const int lane = threadIdx.x & 31;

    if ((int)blockIdx.x < nRowBlocks) {
        const int row = blockIdx.x * 8 + warp;
        if (row < nRows)
            quant_row_warp(W + (size_t)row * D_DIM,
                           g_Wq + (size_t)row * D_DIM,
                           &g_Wscale[row], lane, true);
    } else {
        const int ex = (blockIdx.x - nRowBlocks) * 8 + warp;
        if (ex < B)
            quant_row_warp(features + (size_t)ex * D_DIM,
                           g_fq + (size_t)ex * D_DIM,
                           &g_fscale[ex], lane, false);
    }
}

// 16 int8 x 16 int8 exact dot via 4 dp4a.
__device__ __forceinline__ int dot16(uint4 w, const int* fq) {
    int acc = 0;
    acc = __dp4a((int)w.x, fq[0], acc);
    acc = __dp4a((int)w.y, fq[1], acc);
    acc = __dp4a((int)w.z, fq[2], acc);
    acc = __dp4a((int)w.w, fq[3], acc);
    return acc;
}

__global__ void __launch_bounds__(256)
nsl_main_kernel(const int* __restrict__ targets,
                const int* __restrict__ noises,
                float* __restrict__ out, int B)
{
    const int b    = blockIdx.x;
    const int tid  = threadIdx.x;
    const int warp = tid >> 5;
    const int lane = tid & 31;
    const int str  = g_idx_stride;

    __shared__ float wsum[64];
    __shared__ int   is_last;

    // Prologue: one LDG.128 of pre-quantized features + one scalar scale load.
    int fq[4];
    {
        uint4 f = reinterpret_cast<const uint4*>(g_fq + (size_t)b * D_DIM)[lane];
        fq[0] = (int)f.x; fq[1] = (int)f.y; fq[2] = (int)f.z; fq[3] = (int)f.w;
    }
    const float sf = g_fscale[b];

    const int* tg = targets + (size_t)b * T_TGT * str;
    const int* ns = noises  + (size_t)b * N_NOI * str;

    // Lane r preloads the index for row k = warp + 8*r.
    const int count = (K_TOT - warp + 7) >> 3;   // 19 (warps 0-5) or 18 (warps 6-7)
    int myidx = 0;
    {
        int k = warp + lane * 8;
        if (k < K_TOT)
            myidx = (k < T_TGT) ? tg[k * str] : ns[(k - T_TGT) * str];
    }

    float local = 0.0f;

    // ---- Groups of 8 rows: 8 independent LDG.128 in flight ----
    const int ngroups = count >> 3;              // 2
    for (int p = 0; p < ngroups; p++) {
        const int r = 8 * p;
        int s[8];
        #pragma unroll
        for (int q = 0; q < 8; q++) {
            int idx = __shfl_sync(0xFFFFFFFFu, myidx, r + q);
            uint4 a = __ldcg(&reinterpret_cast<const uint4*>(g_Wq + (size_t)idx * D_DIM)[lane]);
            s[q] = dot16(a, fq);
        }

        // 8-way merged integer butterfly: 16 shuffles.
        #pragma unroll
        for (int q = 0; q < 8; q++)
            s[q] += __shfl_xor_sync(0xFFFFFFFFu, s[q], 16);
        int m0 = (lane & 16) ? s[1] : s[0];
        int m1 = (lane & 16) ? s[3] : s[2];
        int m2 = (lane & 16) ? s[5] : s[4];
        int m3 = (lane & 16) ? s[7] : s[6];
        m0 += __shfl_xor_sync(0xFFFFFFFFu, m0, 8);
        m1 += __shfl_xor_sync(0xFFFFFFFFu, m1, 8);
        m2 += __shfl_xor_sync(0xFFFFFFFFu, m2, 8);
        m3 += __shfl_xor_sync(0xFFFFFFFFu, m3, 8);
        int n0 = (lane & 8) ? m1 : m0;
        int n1 = (lane & 8) ? m3 : m2;
        n0 += __shfl_xor_sync(0xFFFFFFFFu, n0, 4);
        n1 += __shfl_xor_sync(0xFFFFFFFFu, n1, 4);
        int v = (lane & 4) ? n1 : n0;
        v += __shfl_xor_sync(0xFFFFFFFFu, v, 2);
        v += __shfl_xor_sync(0xFFFFFFFFu, v, 1);

        // Lane 4a (a=0..7) holds row rsel = 4*bit2 + 2*bit3 + bit4 of lane.
        int rsel = ((lane >> 2) & 1) * 4 + ((lane >> 3) & 1) * 2 + ((lane >> 4) & 1);
        int idxr = __shfl_sync(0xFFFFFFFFu, myidx, r + rsel);
        if ((lane & 3) == 0) {
            float sw = g_Wscale[idxr];
            int k = warp + 8 * (r + rsel);
            float sgn = (k < T_TGT) ? 1.0f : -1.0f;
            local += log_sigmoid(sgn * (float)v * (sw * sf));
        }
    }

    // ---- Remainder rows (2 or 3) ----
    int r = ngroups * 8;
    if (r + 1 < count) {   // pair
        int i0 = __shfl_sync(0xFFFFFFFFu, myidx, r);
        int i1 = __shfl_sync(0xFFFFFFFFu, myidx, r + 1);
        uint4 a0 = __ldcg(&reinterpret_cast<const uint4*>(g_Wq + (size_t)i0 * D_DIM)[lane]);
        uint4 a1 = __ldcg(&reinterpret_cast<const uint4*>(g_Wq + (size_t)i1 * D_DIM)[lane]);
        int s0 = dot16(a0, fq);
        int s1 = dot16(a1, fq);
        s0 += __shfl_xor_sync(0xFFFFFFFFu, s0, 16);
        s1 += __shfl_xor_sync(0xFFFFFFFFu, s1, 16);
        int m = (lane < 16) ? s0 : s1;
        #pragma unroll
        for (int o = 8; o > 0; o >>= 1)
            m += __shfl_xor_sync(0xFFFFFFFFu, m, o);
        int rowsel = (lane >= 16) ? 1 : 0;
        int idxr = __shfl_sync(0xFFFFFFFFu, myidx, r + rowsel);
        if ((lane & 15) == 0) {
            float sw = g_Wscale[idxr];
            int k = warp + 8 * (r + rowsel);
            float sgn = (k < T_TGT) ? 1.0f : -1.0f;
            local += log_sigmoid(sgn * (float)m * (sw * sf));
        }
        r += 2;
    }
    if (r < count) {       // single
        int i0 = __shfl_sync(0xFFFFFFFFu, myidx, r);
        uint4 a0 = __ldcg(&reinterpret_cast<const uint4*>(g_Wq + (size_t)i0 * D_DIM)[lane]);
        int s0 = dot16(a0, fq);
        #pragma unroll
        for (int o = 16; o > 0; o >>= 1)
            s0 += __shfl_xor_sync(0xFFFFFFFFu, s0, o);
        if (lane == 0) {
            float sw = g_Wscale[i0];
            int k = warp + r * 8;
            float sgn = (k < T_TGT) ? 1.0f : -1.0f;
            local += log_sigmoid(sgn * (float)s0 * (sw * sf));
        }
    }

    if ((lane & 3) == 0)
        wsum[8 * warp + (lane >> 2)] = local;
    __syncthreads();

    if (tid == 0) {
        float s = 0.0f;
        #pragma unroll
        for (int w = 0; w < 64; w++) s += wsum[w];
        g_partials[b] = s;
        __threadfence();
        unsigned v = atomicAdd(&g_count, 1u);
        is_last = (v == (unsigned)(gridDim.x - 1)) ? 1 : 0;
    }
    __syncthreads();

    // Last finished block performs the deterministic final reduction.
    if (is_last) {
        __shared__ float red[256];
        __threadfence();
        float s = 0.0f;
        for (int i = tid; i < B; i += 256)
            s += g_partials[i];
        red[tid] = s;
        __syncthreads();
        #pragma unroll
        for (int stride = 128; stride > 0; stride >>= 1) {
            if (tid < stride) red[tid] += red[tid + stride];
            __syncthreads();
        }
        if (tid == 0) {
            out[0] = -red[0] / (float)K_TOT;
            g_count = 0;   // reset for next graph replay
        }
    }
}

extern "C" void kernel_launch(void* const* d_in, const int* in_sizes, int n_in,
                              void* d_out, int out_size)
{
    const float* features = (const float*)d_in[0];
    const int*   targets  = (const int*)d_in[1];
    const int*   noises   = (const int*)d_in[2];
    const float* W        = (const float*)d_in[3];

    const int B     = in_sizes[0] / D_DIM;        // 2048
    const int nRows = in_sizes[3] / D_DIM;        // 50000

    const int nRowBlocks = (nRows + 7) / 8;       // 6250
    const int nFeaBlocks = (B + 7) / 8;           // 256

    nsl_convert_kernel<<<nRowBlocks + nFeaBlocks, 256>>>(W, features, targets,
                                                         nRows, nRowBlocks, B);
    nsl_main_kernel<<<B, 256>>>(targets, noises, (float*)d_out, B);
}

// round 11
// speedup vs baseline: 1.3290x; 1.1174x over previous
#include <cuda_runtime.h>
#include <cuda_fp16.h>

// Problem constants (reference: B=2048, T=50, N=100, V=50000, D=512)
#define D_DIM 512
#define T_TGT 50
#define N_NOI 100
#define K_TOT 150
#define V_MAX 50000
#define MAX_B 4096
#define WPB   10            // warps per block
#define RPW   15            // rows per warp (10*15 = 150)
#define NTHR  (WPB * 32)    // 320

// Scratch (__device__ globals: allocation APIs are forbidden)
__device__ signed char   g_Wq[(size_t)V_MAX * D_DIM];  // 25.6 MB int8 copy of W
__device__ float         g_Wscale[V_MAX];              // per-row W scale
__device__ signed char   g_fq[(size_t)MAX_B * D_DIM];  // int8 quantized features
__device__ float         g_fscale[MAX_B];              // per-example feature scale
__device__ float         g_partials[MAX_B];
__device__ int           g_idx_stride;                 // 1 = int32 indices, 2 = int64 low word
__device__ unsigned int  g_count;                      // zero-init; reset by last block each call

__device__ __forceinline__ float log_sigmoid(float x) {
    return fminf(x, 0.0f) - __logf(1.0f + __expf(-fabsf(x)));
}

__device__ __forceinline__ unsigned pack4(float x, float y, float z, float w, float inv) {
    int b0 = __float2int_rn(x * inv);
    int b1 = __float2int_rn(y * inv);
    int b2 = __float2int_rn(z * inv);
    int b3 = __float2int_rn(w * inv);
    return (unsigned)(b0 & 0xFF) | ((unsigned)(b1 & 0xFF) << 8) |
           ((unsigned)(b2 & 0xFF) << 16) | ((unsigned)b3 << 24);
}

// One warp quantizes one length-512 fp32 vector to int8 with a single scale.
// Lane owns elements [16*lane, 16*lane+16).
__device__ __forceinline__ void quant_row_warp(const float* __restrict__ src,
                                               signed char* __restrict__ dst,
                                               float* __restrict__ scale_out,
                                               int lane, bool streaming)
{
    const float4* s4 = reinterpret_cast<const float4*>(src);
    float4 v[4];
    #pragma unroll
    for (int j = 0; j < 4; j++)
        v[j] = streaming ? __ldcs(&s4[4 * lane + j]) : s4[4 * lane + j];

    float m = 0.0f;
    #pragma unroll
    for (int j = 0; j < 4; j++) {
        m = fmaxf(m, fabsf(v[j].x)); m = fmaxf(m, fabsf(v[j].y));
        m = fmaxf(m, fabsf(v[j].z)); m = fmaxf(m, fabsf(v[j].w));
    }
    #pragma unroll
    for (int o = 16; o > 0; o >>= 1)
        m = fmaxf(m, __shfl_xor_sync(0xFFFFFFFFu, m, o));

    const float inv = (m > 0.0f) ? 127.0f / m : 0.0f;

    uint4 o4;
    o4.x = pack4(v[0].x, v[0].y, v[0].z, v[0].w, inv);
    o4.y = pack4(v[1].x, v[1].y, v[1].z, v[1].w, inv);
    o4.z = pack4(v[2].x, v[2].y, v[2].z, v[2].w, inv);
    o4.w = pack4(v[3].x, v[3].y, v[3].z, v[3].w, inv);
    reinterpret_cast<uint4*>(dst)[lane] = o4;

    if (lane == 0)
        *scale_out = m * (1.0f / 127.0f);
}

// Blocks [0, nRowBlocks): quantize W rows. Blocks [nRowBlocks, ...): quantize features.
__global__ void __launch_bounds__(256)
nsl_convert_kernel(const float* __restrict__ W, const float* __restrict__ features,
                   const int* __restrict__ t32, int nRows, int nRowBlocks, int B)
{
    if (blockIdx.x == 0 && threadIdx.x == 0) {
        int all_zero = 1;
        #pragma unroll
        for (int i = 0; i < 8; i++)
            if (t32[2 * i + 1] != 0) all_zero = 0;
        g_idx_stride = all_zero ? 2 : 1;   // int64 little-endian => odd words are 0
    }

    const int warp = threadIdx.x >> 5;
    const int lane = threadIdx.x & 31;

    if ((int)blockIdx.x < nRowBlocks) {
        const int row = blockIdx.x * 8 + warp;
        if (row < nRows)
            quant_row_warp(W + (size_t)row * D_DIM,
                           g_Wq + (size_t)row * D_DIM,
                           &g_Wscale[row], lane, true);
    } else {
        const int ex = (blockIdx.x - nRowBlocks) * 8 + warp;
        if (ex < B)
            quant_row_warp(features + (size_t)ex * D_DIM,
                           g_fq + (size_t)ex * D_DIM,
                           &g_fscale[ex], lane, false);
    }
}

// 16 int8 x 16 int8 exact dot via 4 dp4a.
__device__ __forceinline__ int dot16(uint4 w, const int* fq) {
    int acc = 0;
    acc = __dp4a((int)w.x, fq[0], acc);
    acc = __dp4a((int)w.y, fq[1], acc);
    acc = __dp4a((int)w.z, fq[2], acc);
    acc = __dp4a((int)w.w, fq[3], acc);
    return acc;
}

__global__ void __launch_bounds__(NTHR)
nsl_main_kernel(const int* __restrict__ targets,
                const int* __restrict__ noises,
                float* __restrict__ out, int B)
{
    const int b    = blockIdx.x;
    const int tid  = threadIdx.x;
    const int warp = tid >> 5;
    const int lane = tid & 31;
    const int str  = g_idx_stride;

    __shared__ float wsum[WPB];
    __shared__ int   is_last;

    // Prologue: one LDG.128 of pre-quantized features + one scalar scale load.
    int fq[4];
    {
        uint4 f = reinterpret_cast<const uint4*>(g_fq + (size_t)b * D_DIM)[lane];
        fq[0] = (int)f.x; fq[1] = (int)f.y; fq[2] = (int)f.z; fq[3] = (int)f.w;
    }
    const float sf = g_fscale[b];

    const int* tg = targets + (size_t)b * T_TGT * str;
    const int* ns = noises  + (size_t)b * N_NOI * str;

    // Warp w owns rows k in [15w, 15w+15). Lane r (r<15) preloads row 15w+r's index.
    int myidx = 0;
    if (lane < RPW) {
        int k = warp * RPW + lane;
        myidx = (k < T_TGT) ? tg[k * str] : ns[(k - T_TGT) * str];
    }

    // ---- Single burst: 15 independent LDG.128 in flight ----
    int s[RPW];
    #pragma unroll
    for (int q = 0; q < RPW; q++) {
        int idx = __shfl_sync(0xFFFFFFFFu, myidx, q);
        uint4 a = __ldcg(&reinterpret_cast<const uint4*>(g_Wq + (size_t)idx * D_DIM)[lane]);
        s[q] = dot16(a, fq);
    }

    // ---- 15 single-instruction warp reductions (REDUX.SUM, result in all lanes) ----
    int t[RPW];
    #pragma unroll
    for (int q = 0; q < RPW; q++)
        t[q] = __reduce_add_sync(0xFFFFFFFFu, s[q]);

    // Lane r takes row r's total; one parallel logsigmoid pass covers all 15 rows.
    int v = t[0];
    #pragma unroll
    for (int q = 1; q < RPW; q++)
        if (lane == q) v = t[q];

    float local = 0.0f;
    if (lane < RPW) {
        float sw  = g_Wscale[myidx];          // this lane's own row index
        int   k   = warp * RPW + lane;
        float sgn = (k < T_TGT) ? 1.0f : -1.0f;
        local = log_sigmoid(sgn * (float)v * (sw * sf));
    }

    // Sum the 15 lane values within the warp.
    #pragma unroll
    for (int o = 16; o > 0; o >>= 1)
        local += __shfl_xor_sync(0xFFFFFFFFu, local, o);

    if (lane == 0) wsum[warp] = local;
    __syncthreads();

    if (tid == 0) {
        float sum = 0.0f;
        #pragma unroll
        for (int w = 0; w < WPB; w++) sum += wsum[w];
        g_partials[b] = sum;
        __threadfence();
        unsigned c = atomicAdd(&g_count, 1u);
        is_last = (c == (unsigned)(gridDim.x - 1)) ? 1 : 0;
    }
    __syncthreads();

    // Last finished block performs the deterministic final reduction (256 threads).
    if (is_last) {
        __shared__ float red[256];
        __threadfence();
        if (tid < 256) {
            float sum = 0.0f;
            for (int i = tid; i < B; i += 256)
                sum += g_partials[i];
            red[tid] = sum;
        }
        __syncthreads();
        #pragma unroll
        for (int stride = 128; stride > 0; stride >>= 1) {
            if (tid < stride) red[tid] += red[tid + stride];
            __syncthreads();
        }
        if (tid == 0) {
            out[0] = -red[0] / (float)K_TOT;
            g_count = 0;   // reset for next graph replay
        }
    }
}

extern "C" void kernel_launch(void* const* d_in, const int* in_sizes, int n_in,
                              void* d_out, int out_size)
{
    const float* features = (const float*)d_in[0];
    const int*   targets  = (const int*)d_in[1];
    const int*   noises   = (const int*)d_in[2];
    const float* W        = (const float*)d_in[3];

    const int B     = in_sizes[0] / D_DIM;        // 2048
    const int nRows = in_sizes[3] / D_DIM;        // 50000

    const int nRowBlocks = (nRows + 7) / 8;       // 6250
    const int nFeaBlocks = (B + 7) / 8;           // 256

    nsl_convert_kernel<<<nRowBlocks + nFeaBlocks, 256>>>(W, features, targets,
                                                         nRows, nRowBlocks, B);
    nsl_main_kernel<<<B, NTHR>>>(targets, noises, (float*)d_out, B);
}